// round 7
// baseline (speedup 1.0000x reference)
#include <cuda_runtime.h>
#include <math.h>

#define B 64
#define L 2048
#define D 300
#define KW 111
#define V 50000
#define NCHUNK 8         // token chunks per batch row in zacc
#define CTOK 256         // tokens per chunk
#define SGLEN 2160       // 2048 + 2*55 + 2 pad (max idx 2044+111+4=2159)

// ---- device scratch (no allocs allowed) ----
__device__ float2 vg_scr[V];                 // per-vocab normalized class dots
__device__ float  zpart_scr[B*NCHUNK*D];     // zacc partials
__device__ int    cnt_scr[B];                // zacc arrival counters (reset by conv)

// ---------------------------------------------------------------------------
// Kernel 1: per-VOCAB-row normalized class dots (60MB streaming read).
// 8 warps/block, TWO rows per warp; all 6 row-loads issued up front, then one
// combined 6-value butterfly reduction.
// ---------------------------------------------------------------------------
__global__ void vocab_dot_kernel(const float* __restrict__ emb,
                                 const float* __restrict__ cls) {
    __shared__ __align__(16) float sc[2*D];
    __shared__ float cninv[2];
    int tid = threadIdx.x, warp = tid >> 5, lane = tid & 31;

    for (int i = tid; i < 2*D; i += 256) sc[i] = cls[i];
    __syncthreads();
    if (warp < 2) {
        float ss = 0.f;
        for (int d = lane; d < D; d += 32) { float v = sc[warp*D + d]; ss += v*v; }
        #pragma unroll
        for (int o = 16; o > 0; o >>= 1) ss += __shfl_xor_sync(0xffffffffu, ss, o);
        if (lane == 0) cninv[warp] = 1.0f / fmaxf(sqrtf(ss), 1e-12f);
    }
    __syncthreads();

    const float4* c0 = (const float4*)sc;
    const float4* c1 = (const float4*)(sc + D);
    int r = blockIdx.x * 16 + warp * 2;              // grid*16 == V exactly

    const float4* rowA = (const float4*)(emb + (size_t)r * D);
    const float4* rowB = (const float4*)(emb + (size_t)(r+1) * D);
    bool tail = (lane < 11);
    float4 zf = make_float4(0.f,0.f,0.f,0.f);
    float4 A0 = __ldg(rowA + lane);
    float4 A1 = __ldg(rowA + lane + 32);
    float4 A2 = tail ? __ldg(rowA + lane + 64) : zf;
    float4 B0 = __ldg(rowB + lane);
    float4 B1 = __ldg(rowB + lane + 32);
    float4 B2 = tail ? __ldg(rowB + lane + 64) : zf;

    float ssA=0.f, dA0=0.f, dA1=0.f, ssB=0.f, dB0=0.f, dB1=0.f;
    {
        float4 a = c0[lane], bq = c1[lane];
        ssA += A0.x*A0.x + A0.y*A0.y + A0.z*A0.z + A0.w*A0.w;
        dA0 += A0.x*a.x + A0.y*a.y + A0.z*a.z + A0.w*a.w;
        dA1 += A0.x*bq.x + A0.y*bq.y + A0.z*bq.z + A0.w*bq.w;
        ssB += B0.x*B0.x + B0.y*B0.y + B0.z*B0.z + B0.w*B0.w;
        dB0 += B0.x*a.x + B0.y*a.y + B0.z*a.z + B0.w*a.w;
        dB1 += B0.x*bq.x + B0.y*bq.y + B0.z*bq.z + B0.w*bq.w;
    }
    {
        float4 a = c0[lane+32], bq = c1[lane+32];
        ssA += A1.x*A1.x + A1.y*A1.y + A1.z*A1.z + A1.w*A1.w;
        dA0 += A1.x*a.x + A1.y*a.y + A1.z*a.z + A1.w*a.w;
        dA1 += A1.x*bq.x + A1.y*bq.y + A1.z*bq.z + A1.w*bq.w;
        ssB += B1.x*B1.x + B1.y*B1.y + B1.z*B1.z + B1.w*B1.w;
        dB0 += B1.x*a.x + B1.y*a.y + B1.z*a.z + B1.w*a.w;
        dB1 += B1.x*bq.x + B1.y*bq.y + B1.z*bq.z + B1.w*bq.w;
    }
    if (tail) {
        float4 a = c0[lane+64], bq = c1[lane+64];
        ssA += A2.x*A2.x + A2.y*A2.y + A2.z*A2.z + A2.w*A2.w;
        dA0 += A2.x*a.x + A2.y*a.y + A2.z*a.z + A2.w*a.w;
        dA1 += A2.x*bq.x + A2.y*bq.y + A2.z*bq.z + A2.w*bq.w;
        ssB += B2.x*B2.x + B2.y*B2.y + B2.z*B2.z + B2.w*B2.w;
        dB0 += B2.x*a.x + B2.y*a.y + B2.z*a.z + B2.w*a.w;
        dB1 += B2.x*bq.x + B2.y*bq.y + B2.z*bq.z + B2.w*bq.w;
    }
    #pragma unroll
    for (int o = 16; o > 0; o >>= 1) {
        ssA += __shfl_xor_sync(0xffffffffu, ssA, o);
        dA0 += __shfl_xor_sync(0xffffffffu, dA0, o);
        dA1 += __shfl_xor_sync(0xffffffffu, dA1, o);
        ssB += __shfl_xor_sync(0xffffffffu, ssB, o);
        dB0 += __shfl_xor_sync(0xffffffffu, dB0, o);
        dB1 += __shfl_xor_sync(0xffffffffu, dB1, o);
    }
    if (lane == 0) {
        float invA = 1.0f / fmaxf(sqrtf(ssA), 1e-12f);
        float invB = 1.0f / fmaxf(sqrtf(ssB), 1e-12f);
        vg_scr[r]   = make_float2(dA0 * invA * cninv[0], dA1 * invA * cninv[1]);
        vg_scr[r+1] = make_float2(dB0 * invB * cninv[0], dB1 * invB * cninv[1]);
    }
}

// ---------------------------------------------------------------------------
// Kernel 2: gather vg + conv1d(2->2,K=111,pad55) + relu + channel-max + FULL
// softmax -> writes NORMALIZED beta. One block (512 thr) per batch row,
// 4 positions/thread. Also resets zacc's arrival counter for this row.
// (No max-subtraction: s bounded by sum|w|*|g|, exp can't overflow fp32;
//  ratio identical to max-subtracted softmax.)
// ---------------------------------------------------------------------------
__global__ void conv_softmax_kernel(const int* __restrict__ inputs,
                                    const float* __restrict__ conv_w,
                                    const float* __restrict__ conv_b,
                                    float* __restrict__ out, int beta_off) {
    __shared__ float sg0[SGLEN], sg1[SGLEN], sw[448], sred[512];
    int b = blockIdx.x, tid = threadIdx.x;
    if (tid == 0) cnt_scr[b] = 0;                        // stream-ordered before zacc

    for (int i = tid; i < SGLEN; i += 512) { sg0[i] = 0.f; sg1[i] = 0.f; }
    for (int t = tid; t < 448; t += 512) {               // weights padded K=112
        int k = t % 112, ci = (t/112) & 1, o = t/224;
        sw[t] = (k < KW) ? conv_w[o*2*KW + ci*KW + k] : 0.f;
    }
    __syncthreads();
    for (int l = tid; l < L; l += 512) {
        float2 g = __ldg(&vg_scr[inputs[b*L + l]]);
        sg0[55+l] = g.x; sg1[55+l] = g.y;
    }
    __syncthreads();

    float cb0 = __ldg(conv_b + 0), cb1 = __ldg(conv_b + 1);
    int lp0 = tid * 4;
    float a0[4], a1[4], x0[4], x1[4];
    #pragma unroll
    for (int p = 0; p < 4; p++) {
        a0[p] = cb0; a1[p] = cb1;
        x0[p] = sg0[lp0+p]; x1[p] = sg1[lp0+p];
    }
    #pragma unroll 8
    for (int k = 0; k < 112; k++) {
        float w00 = sw[k], w01 = sw[112+k], w10 = sw[224+k], w11 = sw[336+k];
        #pragma unroll
        for (int p = 0; p < 4; p++) {
            float v0 = x0[(k+p)&3], v1 = x1[(k+p)&3];
            a0[p] += w00*v0 + w01*v1;
            a1[p] += w10*v0 + w11*v1;
        }
        x0[k&3] = sg0[lp0+k+4];
        x1[k&3] = sg1[lp0+k+4];
    }

    float e[4]; float lsum = 0.f;
    #pragma unroll
    for (int p = 0; p < 4; p++) {
        float s = fmaxf(0.f, fmaxf(a0[p], a1[p]));   // max(relu(a0),relu(a1))
        e[p] = expf(s);
        lsum += e[p];
    }
    sred[tid] = lsum; __syncthreads();
    for (int st = 256; st > 0; st >>= 1) {
        if (tid < st) sred[tid] += sred[tid+st];
        __syncthreads();
    }
    float inv = 1.0f / sred[0];

    float* bout = out + beta_off + b*L + lp0;
    #pragma unroll
    for (int p = 0; p < 4; p++) bout[p] = e[p]*inv;
}

// ---------------------------------------------------------------------------
// Kernel 3 (fused): zpart[b,chunk,:] = sum_{l in chunk} beta*emb[idx]; the
// LAST arriving block of each batch row reduces all chunks and emits logits.
// 608 thr = 8 groups x 75 float4 lanes; group accumulates 32 tokens (MLP 8).
// Staging stores precomputed byte offsets (idx*1200 < 2^31).
// ---------------------------------------------------------------------------
__global__ void zacc_logits_kernel(const int* __restrict__ inputs,
                                   const float* __restrict__ emb,
                                   const float* __restrict__ lin_w,
                                   const float* __restrict__ lin_b,
                                   float* __restrict__ out, int beta_off) {
    __shared__ int   soff[CTOK];
    __shared__ float sb[CTOK];
    __shared__ __align__(16) float4 sacc[8][75];
    __shared__ float sr0[128], sr1[128];
    __shared__ int isLast;
    int b = blockIdx.x, chunk = blockIdx.y, tid = threadIdx.x;
    int l0 = chunk * CTOK;
    if (tid < CTOK) {
        soff[tid] = inputs[b*L + l0 + tid] * (int)(D * sizeof(float));
        sb[tid]   = out[beta_off + b*L + l0 + tid];     // already normalized
    }
    __syncthreads();

    int g = tid / 75;              // group 0..7 (tid<600), rest idle
    int q = tid - g * 75;          // float4 lane 0..74
    if (g < 8) {
        float4 acc = make_float4(0.f, 0.f, 0.f, 0.f);
        int t0 = g * 32;
        #pragma unroll 8
        for (int i = 0; i < 32; i++) {
            int t = t0 + i;
            const float4* row = (const float4*)((const char*)emb + soff[t]);
            float w = sb[t];
            float4 v = __ldg(row + q);
            acc.x += w*v.x; acc.y += w*v.y; acc.z += w*v.z; acc.w += w*v.w;
        }
        sacc[g][q] = acc;
    }
    __syncthreads();

    if (tid < 75) {
        float4 s = make_float4(0.f, 0.f, 0.f, 0.f);
        #pragma unroll
        for (int gg = 0; gg < 8; gg++) {
            float4 a = sacc[gg][tid];
            s.x += a.x; s.y += a.y; s.z += a.z; s.w += a.w;
        }
        ((float4*)&zpart_scr[(b*NCHUNK + chunk) * D])[tid] = s;
        __threadfence();                                  // publish before arrival
    }
    __syncthreads();
    if (tid == 0) {
        int old = atomicAdd(&cnt_scr[b], 1);
        isLast = (old == NCHUNK - 1);
    }
    __syncthreads();
    if (!isLast) return;

    // ---- logits tail (runs once per batch row, zpart L2-hot) ----
    if (tid < 128) { sr0[tid] = 0.f; sr1[tid] = 0.f; }
    __syncthreads();
    if (tid < 75) {
        float4 z = make_float4(0.f, 0.f, 0.f, 0.f);
        #pragma unroll
        for (int c = 0; c < NCHUNK; c++) {
            float4 p = ((const float4*)&zpart_scr[(b*NCHUNK + c) * D])[tid];
            z.x += p.x; z.y += p.y; z.z += p.z; z.w += p.w;
        }
        float4 w0 = __ldg((const float4*)lin_w + tid);
        float4 w1 = __ldg((const float4*)(lin_w + D) + tid);
        sr0[tid] = z.x*w0.x + z.y*w0.y + z.z*w0.z + z.w*w0.w;
        sr1[tid] = z.x*w1.x + z.y*w1.y + z.z*w1.z + z.w*w1.w;
    }
    __syncthreads();
    for (int st = 64; st > 0; st >>= 1) {
        if (tid < st) { sr0[tid] += sr0[tid+st]; sr1[tid] += sr1[tid+st]; }
        __syncthreads();
    }
    if (tid == 0) {
        float a = sr0[0] + __ldg(lin_b + 0);
        float c = sr1[0] + __ldg(lin_b + 1);
        float m = fmaxf(a, c);
        float lse = m + logf(expf(a - m) + expf(c - m));
        out[b*2 + 0] = a - lse;
        out[b*2 + 1] = c - lse;
    }
}

// ---------------------------------------------------------------------------
extern "C" void kernel_launch(void* const* d_in, const int* in_sizes, int n_in,
                              void* d_out, int out_size) {
    const int*   inputs  = (const int*)  d_in[0];
    const float* emb     = (const float*)d_in[1];
    const float* cls     = (const float*)d_in[2];
    const float* conv_w  = (const float*)d_in[3];
    const float* conv_b  = (const float*)d_in[4];
    const float* lin_w   = (const float*)d_in[5];
    const float* lin_b   = (const float*)d_in[6];
    float* out = (float*)d_out;

    int beta_off = out_size - B*L;   // logits first, then beta [B,L]

    vocab_dot_kernel<<<V/16, 256>>>(emb, cls);                         // 3125 blocks
    conv_softmax_kernel<<<B, 512>>>(inputs, conv_w, conv_b, out, beta_off);
    zacc_logits_kernel<<<dim3(B, NCHUNK), 608>>>(inputs, emb, lin_w, lin_b, out, beta_off);
}

// round 8
// speedup vs baseline: 1.0148x; 1.0148x over previous
#include <cuda_runtime.h>
#include <cuda_fp16.h>
#include <math.h>

#define B 64
#define L 2048
#define D 300
#define KW 111
#define V 50000
#define NCHUNK 8         // token chunks per batch row in zacc
#define CTOK 256         // tokens per chunk
#define HL 1024          // conv half-length per block
#define SG2 1140         // halo'd shared length: 1024 + 111 + 4 + pad

// ---- device scratch (no allocs allowed) ----
__device__ float2 vg_scr[V];                 // per-vocab normalized class dots
__device__ __half emb_h[(size_t)V*D];        // fp16 table copy (30MB), 600B rows
__device__ float  zpart_scr[B*NCHUNK*D];     // zacc partials (no atomics)
__device__ float  esum_scr[B*2];             // per-half exp-sum partials

__device__ __forceinline__ void store_h8(__half* dst, float4 v) {
    __half2 h0 = __floats2half2_rn(v.x, v.y);
    __half2 h1 = __floats2half2_rn(v.z, v.w);
    uint2 u;
    u.x = *reinterpret_cast<unsigned*>(&h0);
    u.y = *reinterpret_cast<unsigned*>(&h1);
    *reinterpret_cast<uint2*>(dst) = u;      // 8B store, dst 8B-aligned
}

// ---------------------------------------------------------------------------
// Kernel 1: per-VOCAB-row normalized class dots (60MB streaming read) and
// fp16 table conversion (30MB write, data already in registers).
// 8 warps/block, TWO rows per warp; all 6 row-loads issued up front.
// ---------------------------------------------------------------------------
__global__ void vocab_dot_kernel(const float* __restrict__ emb,
                                 const float* __restrict__ cls) {
    __shared__ __align__(16) float sc[2*D];
    __shared__ float cninv[2];
    int tid = threadIdx.x, warp = tid >> 5, lane = tid & 31;

    for (int i = tid; i < 2*D; i += 256) sc[i] = cls[i];
    __syncthreads();
    if (warp < 2) {
        float ss = 0.f;
        for (int d = lane; d < D; d += 32) { float v = sc[warp*D + d]; ss += v*v; }
        #pragma unroll
        for (int o = 16; o > 0; o >>= 1) ss += __shfl_xor_sync(0xffffffffu, ss, o);
        if (lane == 0) cninv[warp] = 1.0f / fmaxf(sqrtf(ss), 1e-12f);
    }
    __syncthreads();

    const float4* c0 = (const float4*)sc;
    const float4* c1 = (const float4*)(sc + D);
    int r = blockIdx.x * 16 + warp * 2;              // grid*16 == V exactly

    const float4* rowA = (const float4*)(emb + (size_t)r * D);
    const float4* rowB = (const float4*)(emb + (size_t)(r+1) * D);
    bool tail = (lane < 11);
    float4 zf = make_float4(0.f,0.f,0.f,0.f);
    float4 A0 = __ldg(rowA + lane);
    float4 A1 = __ldg(rowA + lane + 32);
    float4 A2 = tail ? __ldg(rowA + lane + 64) : zf;
    float4 B0 = __ldg(rowB + lane);
    float4 B1 = __ldg(rowB + lane + 32);
    float4 B2 = tail ? __ldg(rowB + lane + 64) : zf;

    // fp16 table conversion (fire-and-forget stores)
    __half* hA = &emb_h[(size_t)r * D];
    __half* hB = &emb_h[(size_t)(r+1) * D];
    store_h8(hA + 4*lane,        A0);
    store_h8(hA + 4*(lane+32),   A1);
    if (tail) store_h8(hA + 4*(lane+64), A2);
    store_h8(hB + 4*lane,        B0);
    store_h8(hB + 4*(lane+32),   B1);
    if (tail) store_h8(hB + 4*(lane+64), B2);

    float ssA=0.f, dA0=0.f, dA1=0.f, ssB=0.f, dB0=0.f, dB1=0.f;
    {
        float4 a = c0[lane], bq = c1[lane];
        ssA += A0.x*A0.x + A0.y*A0.y + A0.z*A0.z + A0.w*A0.w;
        dA0 += A0.x*a.x + A0.y*a.y + A0.z*a.z + A0.w*a.w;
        dA1 += A0.x*bq.x + A0.y*bq.y + A0.z*bq.z + A0.w*bq.w;
        ssB += B0.x*B0.x + B0.y*B0.y + B0.z*B0.z + B0.w*B0.w;
        dB0 += B0.x*a.x + B0.y*a.y + B0.z*a.z + B0.w*a.w;
        dB1 += B0.x*bq.x + B0.y*bq.y + B0.z*bq.z + B0.w*bq.w;
    }
    {
        float4 a = c0[lane+32], bq = c1[lane+32];
        ssA += A1.x*A1.x + A1.y*A1.y + A1.z*A1.z + A1.w*A1.w;
        dA0 += A1.x*a.x + A1.y*a.y + A1.z*a.z + A1.w*a.w;
        dA1 += A1.x*bq.x + A1.y*bq.y + A1.z*bq.z + A1.w*bq.w;
        ssB += B1.x*B1.x + B1.y*B1.y + B1.z*B1.z + B1.w*B1.w;
        dB0 += B1.x*a.x + B1.y*a.y + B1.z*a.z + B1.w*a.w;
        dB1 += B1.x*bq.x + B1.y*bq.y + B1.z*bq.z + B1.w*bq.w;
    }
    if (tail) {
        float4 a = c0[lane+64], bq = c1[lane+64];
        ssA += A2.x*A2.x + A2.y*A2.y + A2.z*A2.z + A2.w*A2.w;
        dA0 += A2.x*a.x + A2.y*a.y + A2.z*a.z + A2.w*a.w;
        dA1 += A2.x*bq.x + A2.y*bq.y + A2.z*bq.z + A2.w*bq.w;
        ssB += B2.x*B2.x + B2.y*B2.y + B2.z*B2.z + B2.w*B2.w;
        dB0 += B2.x*a.x + B2.y*a.y + B2.z*a.z + B2.w*a.w;
        dB1 += B2.x*bq.x + B2.y*bq.y + B2.z*bq.z + B2.w*bq.w;
    }
    #pragma unroll
    for (int o = 16; o > 0; o >>= 1) {
        ssA += __shfl_xor_sync(0xffffffffu, ssA, o);
        dA0 += __shfl_xor_sync(0xffffffffu, dA0, o);
        dA1 += __shfl_xor_sync(0xffffffffu, dA1, o);
        ssB += __shfl_xor_sync(0xffffffffu, ssB, o);
        dB0 += __shfl_xor_sync(0xffffffffu, dB0, o);
        dB1 += __shfl_xor_sync(0xffffffffu, dB1, o);
    }
    if (lane == 0) {
        float invA = 1.0f / fmaxf(sqrtf(ssA), 1e-12f);
        float invB = 1.0f / fmaxf(sqrtf(ssB), 1e-12f);
        vg_scr[r]   = make_float2(dA0 * invA * cninv[0], dA1 * invA * cninv[1]);
        vg_scr[r+1] = make_float2(dB0 * invB * cninv[0], dB1 * invB * cninv[1]);
    }
}

// ---------------------------------------------------------------------------
// Kernel 2: gather vg + conv1d(2->2,K=111,pad55) + relu + channel-max + exp.
// grid (B, 2): each block handles 1024 positions (+55 halo each side).
// Writes UNNORMALIZED e=exp(s) + per-half sum to scratch. (exp can't overflow
// fp32; ratio identical to max-subtracted softmax.)
// ---------------------------------------------------------------------------
__global__ void conv_exp_kernel(const int* __restrict__ inputs,
                                const float* __restrict__ conv_w,
                                const float* __restrict__ conv_b,
                                float* __restrict__ out, int beta_off) {
    __shared__ float sg0[SG2], sg1[SG2], sw[448], sred[256];
    int b = blockIdx.x, half = blockIdx.y, tid = threadIdx.x;
    int l0 = half * HL;

    for (int i = tid; i < SG2; i += 256) { sg0[i] = 0.f; sg1[i] = 0.f; }
    for (int t = tid; t < 448; t += 256) {                 // weights padded K=112
        int k = t % 112, ci = (t/112) & 1, o = t/224;
        sw[t] = (k < KW) ? conv_w[o*2*KW + ci*KW + k] : 0.f;
    }
    __syncthreads();
    for (int i = tid; i < HL + 111; i += 256) {
        int gl = l0 - 55 + i;
        if (gl >= 0 && gl < L) {
            float2 g = __ldg(&vg_scr[inputs[b*L + gl]]);
            sg0[i] = g.x; sg1[i] = g.y;
        }
    }
    __syncthreads();

    float cb0 = __ldg(conv_b + 0), cb1 = __ldg(conv_b + 1);
    int lp0 = tid * 4;
    float a0[4], a1[4], x0[4], x1[4];
    #pragma unroll
    for (int p = 0; p < 4; p++) {
        a0[p] = cb0; a1[p] = cb1;
        x0[p] = sg0[lp0+p]; x1[p] = sg1[lp0+p];
    }
    #pragma unroll 8
    for (int k = 0; k < 112; k++) {
        float w00 = sw[k], w01 = sw[112+k], w10 = sw[224+k], w11 = sw[336+k];
        #pragma unroll
        for (int p = 0; p < 4; p++) {
            float v0 = x0[(k+p)&3], v1 = x1[(k+p)&3];
            a0[p] += w00*v0 + w01*v1;
            a1[p] += w10*v0 + w11*v1;
        }
        x0[k&3] = sg0[lp0+k+4];
        x1[k&3] = sg1[lp0+k+4];
    }

    float e[4]; float lsum = 0.f;
    #pragma unroll
    for (int p = 0; p < 4; p++) {
        float s = fmaxf(0.f, fmaxf(a0[p], a1[p]));   // max(relu(a0),relu(a1))
        e[p] = expf(s);
        lsum += e[p];
    }
    float* bout = out + beta_off + b*L + l0 + lp0;
    #pragma unroll
    for (int p = 0; p < 4; p++) bout[p] = e[p];

    sred[tid] = lsum; __syncthreads();
    for (int st = 128; st > 0; st >>= 1) {
        if (tid < st) sred[tid] += sred[tid+st];
        __syncthreads();
    }
    if (tid == 0) esum_scr[b*2 + half] = sred[0];
}

// ---------------------------------------------------------------------------
// Kernel 3: zpart[b,chunk,:] = sum_{l in chunk} beta[b,l]*emb_h[inputs[b,l]]
// fp16 gather: 600B/row (half the fp32 traffic). 608 thr = 8 groups x 75
// lanes; lane q loads 8B (4 halves) per token; group does 32 tokens (MLP 8).
// Normalizes beta on the fly and writes normalized beta back in-place.
// ---------------------------------------------------------------------------
__global__ void zacc_kernel(const int* __restrict__ inputs,
                            float* __restrict__ out, int beta_off) {
    __shared__ int   soff[CTOK];
    __shared__ float sb[CTOK];
    __shared__ __align__(16) float4 sacc[8][75];
    int b = blockIdx.x, chunk = blockIdx.y, tid = threadIdx.x;
    int l0 = chunk * CTOK;
    float invsum = 1.0f / (esum_scr[b*2] + esum_scr[b*2+1]);
    if (tid < CTOK) {
        soff[tid] = inputs[b*L + l0 + tid] * (int)(D * sizeof(__half));  // byte off
        float w = out[beta_off + b*L + l0 + tid] * invsum;
        sb[tid] = w;
        out[beta_off + b*L + l0 + tid] = w;     // normalized beta, final
    }
    __syncthreads();

    int g = tid / 75;              // group 0..7 (tid<600), rest idle
    int q = tid - g * 75;          // 8B lane 0..74 (covers elements 4q..4q+3)
    if (g < 8) {
        float4 acc = make_float4(0.f, 0.f, 0.f, 0.f);
        int t0 = g * 32;
        #pragma unroll 8
        for (int i = 0; i < 32; i++) {
            int t = t0 + i;
            const uint2* row = (const uint2*)((const char*)emb_h + soff[t]);
            float w = sb[t];
            uint2 u = __ldg(row + q);
            __half2 h0 = *reinterpret_cast<__half2*>(&u.x);
            __half2 h1 = *reinterpret_cast<__half2*>(&u.y);
            float2 f0 = __half22float2(h0);
            float2 f1 = __half22float2(h1);
            acc.x += w*f0.x; acc.y += w*f0.y; acc.z += w*f1.x; acc.w += w*f1.y;
        }
        sacc[g][q] = acc;
    }
    __syncthreads();

    if (tid < 75) {
        float4 s = make_float4(0.f, 0.f, 0.f, 0.f);
        #pragma unroll
        for (int gg = 0; gg < 8; gg++) {
            float4 a = sacc[gg][tid];
            s.x += a.x; s.y += a.y; s.z += a.z; s.w += a.w;
        }
        ((float4*)&zpart_scr[(b*NCHUNK + chunk) * D])[tid] = s;
    }
}

// ---------------------------------------------------------------------------
// Kernel 4: reduce zpart over chunks + logits = log_softmax(z@W^T + b).
// 608 thr: 8 groups x 75 lanes, one chunk per group, shared reduce + dot.
// ---------------------------------------------------------------------------
__global__ void logits_kernel(const float* __restrict__ lin_w,
                              const float* __restrict__ lin_b,
                              float* __restrict__ out) {
    __shared__ __align__(16) float4 sz[8][75];
    __shared__ float sr0[128], sr1[128];
    int b = blockIdx.x, tid = threadIdx.x;
    int g = tid / 75, q = tid - g * 75;
    if (g < 8)
        sz[g][q] = ((const float4*)&zpart_scr[(b*NCHUNK + g) * D])[q];
    __syncthreads();

    if (tid < 128) { sr0[tid] = 0.f; sr1[tid] = 0.f; }
    __syncthreads();
    if (tid < 75) {
        float4 z = make_float4(0.f, 0.f, 0.f, 0.f);
        #pragma unroll
        for (int gg = 0; gg < 8; gg++) {
            float4 p = sz[gg][tid];
            z.x += p.x; z.y += p.y; z.z += p.z; z.w += p.w;
        }
        float4 w0 = __ldg((const float4*)lin_w + tid);
        float4 w1 = __ldg((const float4*)(lin_w + D) + tid);
        sr0[tid] = z.x*w0.x + z.y*w0.y + z.z*w0.z + z.w*w0.w;
        sr1[tid] = z.x*w1.x + z.y*w1.y + z.z*w1.z + z.w*w1.w;
    }
    __syncthreads();
    for (int st = 64; st > 0; st >>= 1) {
        if (tid < st) { sr0[tid] += sr0[tid+st]; sr1[tid] += sr1[tid+st]; }
        __syncthreads();
    }
    if (tid == 0) {
        float a = sr0[0] + __ldg(lin_b + 0);
        float c = sr1[0] + __ldg(lin_b + 1);
        float m = fmaxf(a, c);
        float lse = m + logf(expf(a - m) + expf(c - m));
        out[b*2 + 0] = a - lse;
        out[b*2 + 1] = c - lse;
    }
}

// ---------------------------------------------------------------------------
extern "C" void kernel_launch(void* const* d_in, const int* in_sizes, int n_in,
                              void* d_out, int out_size) {
    const int*   inputs  = (const int*)  d_in[0];
    const float* emb     = (const float*)d_in[1];
    const float* cls     = (const float*)d_in[2];
    const float* conv_w  = (const float*)d_in[3];
    const float* conv_b  = (const float*)d_in[4];
    const float* lin_w   = (const float*)d_in[5];
    const float* lin_b   = (const float*)d_in[6];
    float* out = (float*)d_out;

    int beta_off = out_size - B*L;   // logits first, then beta [B,L]

    vocab_dot_kernel<<<V/16, 256>>>(emb, cls);                         // 3125 blocks
    conv_exp_kernel<<<dim3(B, 2), 256>>>(inputs, conv_w, conv_b, out, beta_off);
    zacc_kernel<<<dim3(B, NCHUNK), 608>>>(inputs, out, beta_off);
    logits_kernel<<<B, 608>>>(lin_w, lin_b, out);
}

// round 9
// speedup vs baseline: 1.1169x; 1.1006x over previous
#include <cuda_runtime.h>
#include <math.h>

#define B 64
#define L 2048
#define D 300
#define KW 111
#define V 50000
#define NCHUNK 8         // token chunks per batch row in zacc
#define CTOK 256         // tokens per chunk
#define HL 1024          // conv half-length per block
#define SG2 1140         // halo'd shared length: 1024 + 111 + 4 + pad

// ---- device scratch (no allocs allowed) ----
__device__ float2 vg_scr[V];                 // per-vocab normalized class dots
__device__ float  zpart_scr[B*NCHUNK*D];     // zacc partials (no atomics)
__device__ float  esum_scr[B*2];             // per-half exp-sum partials

__device__ __forceinline__ void acc3(float4 e, float4 ka, float4 kb,
                                     float& ss, float& d0, float& d1) {
    ss += e.x*e.x + e.y*e.y + e.z*e.z + e.w*e.w;
    d0 += e.x*ka.x + e.y*ka.y + e.z*ka.z + e.w*ka.w;
    d1 += e.x*kb.x + e.y*kb.y + e.z*kb.z + e.w*kb.w;
}

// ---------------------------------------------------------------------------
// Kernel 1: per-VOCAB-row normalized class dots (60MB streaming read).
// FOUR rows per warp, all 12 float4 loads issued before any math; class
// vectors hoisted to registers; combined 12-value butterfly reduction.
// ---------------------------------------------------------------------------
__global__ void __launch_bounds__(256)
vocab_dot_kernel(const float* __restrict__ emb, const float* __restrict__ cls) {
    __shared__ __align__(16) float sc[2*D];
    __shared__ float cninv[2];
    int tid = threadIdx.x, warp = tid >> 5, lane = tid & 31;

    for (int i = tid; i < 2*D; i += 256) sc[i] = cls[i];
    __syncthreads();
    if (warp < 2) {
        float ss = 0.f;
        for (int d = lane; d < D; d += 32) { float v = sc[warp*D + d]; ss += v*v; }
        #pragma unroll
        for (int o = 16; o > 0; o >>= 1) ss += __shfl_xor_sync(0xffffffffu, ss, o);
        if (lane == 0) cninv[warp] = 1.0f / fmaxf(sqrtf(ss), 1e-12f);
    }
    __syncthreads();

    const float4* c0 = (const float4*)sc;
    const float4* c1 = (const float4*)(sc + D);
    bool tail = (lane < 11);
    float4 zf = make_float4(0.f,0.f,0.f,0.f);

    // class vectors: load once to registers, reused by all 4 rows
    float4 k0 = c0[lane], k1 = c0[lane+32], k2 = tail ? c0[lane+64] : zf;
    float4 m0 = c1[lane], m1 = c1[lane+32], m2 = tail ? c1[lane+64] : zf;

    int rbase = blockIdx.x * 32 + warp * 4;          // 4 rows per warp
    int r0 = min(rbase,     V-1);
    int r1 = min(rbase + 1, V-1);
    int r2 = min(rbase + 2, V-1);
    int r3 = min(rbase + 3, V-1);
    const float4* p0 = (const float4*)(emb + (size_t)r0 * D);
    const float4* p1 = (const float4*)(emb + (size_t)r1 * D);
    const float4* p2 = (const float4*)(emb + (size_t)r2 * D);
    const float4* p3 = (const float4*)(emb + (size_t)r3 * D);

    // issue ALL 12 loads before any math
    float4 A0 = __ldg(p0 + lane), A1 = __ldg(p0 + lane + 32), A2 = tail ? __ldg(p0 + lane + 64) : zf;
    float4 B0 = __ldg(p1 + lane), B1 = __ldg(p1 + lane + 32), B2 = tail ? __ldg(p1 + lane + 64) : zf;
    float4 C0 = __ldg(p2 + lane), C1 = __ldg(p2 + lane + 32), C2 = tail ? __ldg(p2 + lane + 64) : zf;
    float4 D0 = __ldg(p3 + lane), D1 = __ldg(p3 + lane + 32), D2 = tail ? __ldg(p3 + lane + 64) : zf;

    float v[12];
    #pragma unroll
    for (int i = 0; i < 12; i++) v[i] = 0.f;
    acc3(A0, k0, m0, v[0], v[1], v[2]);  acc3(A1, k1, m1, v[0], v[1], v[2]);
    acc3(B0, k0, m0, v[3], v[4], v[5]);  acc3(B1, k1, m1, v[3], v[4], v[5]);
    acc3(C0, k0, m0, v[6], v[7], v[8]);  acc3(C1, k1, m1, v[6], v[7], v[8]);
    acc3(D0, k0, m0, v[9], v[10], v[11]); acc3(D1, k1, m1, v[9], v[10], v[11]);
    if (tail) {
        acc3(A2, k2, m2, v[0], v[1], v[2]);
        acc3(B2, k2, m2, v[3], v[4], v[5]);
        acc3(C2, k2, m2, v[6], v[7], v[8]);
        acc3(D2, k2, m2, v[9], v[10], v[11]);
    }

    #pragma unroll
    for (int o = 16; o > 0; o >>= 1) {
        #pragma unroll
        for (int i = 0; i < 12; i++)
            v[i] += __shfl_xor_sync(0xffffffffu, v[i], o);
    }

    if (lane == 0) {
        float cn0 = cninv[0], cn1 = cninv[1];
        #pragma unroll
        for (int i = 0; i < 4; i++) {
            int r = rbase + i;
            if (r < V) {
                float inv = 1.0f / fmaxf(sqrtf(v[3*i]), 1e-12f);
                vg_scr[r] = make_float2(v[3*i+1] * inv * cn0, v[3*i+2] * inv * cn1);
            }
        }
    }
}

// ---------------------------------------------------------------------------
// Kernel 2: gather vg + conv1d(2->2,K=111,pad55) + relu + channel-max + exp.
// grid (B, 2): each block handles 1024 positions (+55 halo each side).
// Writes UNNORMALIZED e=exp(s) + per-half sum to scratch. (exp can't overflow
// fp32; ratio identical to max-subtracted softmax.)
// ---------------------------------------------------------------------------
__global__ void conv_exp_kernel(const int* __restrict__ inputs,
                                const float* __restrict__ conv_w,
                                const float* __restrict__ conv_b,
                                float* __restrict__ out, int beta_off) {
    __shared__ float sg0[SG2], sg1[SG2], sw[448], sred[256];
    int b = blockIdx.x, half = blockIdx.y, tid = threadIdx.x;
    int l0 = half * HL;

    for (int i = tid; i < SG2; i += 256) { sg0[i] = 0.f; sg1[i] = 0.f; }
    for (int t = tid; t < 448; t += 256) {                 // weights padded K=112
        int k = t % 112, ci = (t/112) & 1, o = t/224;
        sw[t] = (k < KW) ? conv_w[o*2*KW + ci*KW + k] : 0.f;
    }
    __syncthreads();
    for (int i = tid; i < HL + 111; i += 256) {
        int gl = l0 - 55 + i;
        if (gl >= 0 && gl < L) {
            float2 g = __ldg(&vg_scr[inputs[b*L + gl]]);
            sg0[i] = g.x; sg1[i] = g.y;
        }
    }
    __syncthreads();

    float cb0 = __ldg(conv_b + 0), cb1 = __ldg(conv_b + 1);
    int lp0 = tid * 4;
    float a0[4], a1[4], x0[4], x1[4];
    #pragma unroll
    for (int p = 0; p < 4; p++) {
        a0[p] = cb0; a1[p] = cb1;
        x0[p] = sg0[lp0+p]; x1[p] = sg1[lp0+p];
    }
    #pragma unroll 8
    for (int k = 0; k < 112; k++) {
        float w00 = sw[k], w01 = sw[112+k], w10 = sw[224+k], w11 = sw[336+k];
        #pragma unroll
        for (int p = 0; p < 4; p++) {
            float v0 = x0[(k+p)&3], v1 = x1[(k+p)&3];
            a0[p] += w00*v0 + w01*v1;
            a1[p] += w10*v0 + w11*v1;
        }
        x0[k&3] = sg0[lp0+k+4];
        x1[k&3] = sg1[lp0+k+4];
    }

    float e[4]; float lsum = 0.f;
    #pragma unroll
    for (int p = 0; p < 4; p++) {
        float s = fmaxf(0.f, fmaxf(a0[p], a1[p]));   // max(relu(a0),relu(a1))
        e[p] = expf(s);
        lsum += e[p];
    }
    float* bout = out + beta_off + b*L + l0 + lp0;
    #pragma unroll
    for (int p = 0; p < 4; p++) bout[p] = e[p];

    sred[tid] = lsum; __syncthreads();
    for (int st = 128; st > 0; st >>= 1) {
        if (tid < st) sred[tid] += sred[tid+st];
        __syncthreads();
    }
    if (tid == 0) esum_scr[b*2 + half] = sred[0];
}

// ---------------------------------------------------------------------------
// Kernel 3: zpart[b,chunk,:] = sum_{l in chunk} beta[b,l]*emb[inputs[b,l]]
// 608 thr = 8 groups x 75 float4 lanes; group accumulates 32 tokens (MLP 8).
// Normalizes beta on the fly and writes normalized beta back in-place.
// ---------------------------------------------------------------------------
__global__ void zacc_kernel(const int* __restrict__ inputs,
                            const float* __restrict__ emb,
                            float* __restrict__ out, int beta_off) {
    __shared__ int   soff[CTOK];
    __shared__ float sb[CTOK];
    __shared__ __align__(16) float4 sacc[8][75];
    int b = blockIdx.x, chunk = blockIdx.y, tid = threadIdx.x;
    int l0 = chunk * CTOK;
    float invsum = 1.0f / (esum_scr[b*2] + esum_scr[b*2+1]);
    if (tid < CTOK) {
        soff[tid] = inputs[b*L + l0 + tid] * (int)(D * sizeof(float));
        float w = out[beta_off + b*L + l0 + tid] * invsum;
        sb[tid] = w;
        out[beta_off + b*L + l0 + tid] = w;     // normalized beta, final
    }
    __syncthreads();

    int g = tid / 75;              // group 0..7 (tid<600), rest idle
    int q = tid - g * 75;          // float4 lane 0..74
    if (g < 8) {
        float4 acc = make_float4(0.f, 0.f, 0.f, 0.f);
        int t0 = g * 32;
        #pragma unroll 8
        for (int i = 0; i < 32; i++) {
            int t = t0 + i;
            const float4* row = (const float4*)((const char*)emb + soff[t]);
            float w = sb[t];
            float4 v = __ldg(row + q);
            acc.x += w*v.x; acc.y += w*v.y; acc.z += w*v.z; acc.w += w*v.w;
        }
        sacc[g][q] = acc;
    }
    __syncthreads();

    if (tid < 75) {
        float4 s = make_float4(0.f, 0.f, 0.f, 0.f);
        #pragma unroll
        for (int gg = 0; gg < 8; gg++) {
            float4 a = sacc[gg][tid];
            s.x += a.x; s.y += a.y; s.z += a.z; s.w += a.w;
        }
        ((float4*)&zpart_scr[(b*NCHUNK + chunk) * D])[tid] = s;
    }
}

// ---------------------------------------------------------------------------
// Kernel 4: reduce zpart over chunks + logits = log_softmax(z@W^T + b).
// 608 thr: 8 groups x 75 lanes, one chunk per group, shared reduce + dot.
// ---------------------------------------------------------------------------
__global__ void logits_kernel(const float* __restrict__ lin_w,
                              const float* __restrict__ lin_b,
                              float* __restrict__ out) {
    __shared__ __align__(16) float4 sz[8][75];
    __shared__ float sr0[128], sr1[128];
    int b = blockIdx.x, tid = threadIdx.x;
    int g = tid / 75, q = tid - g * 75;
    if (g < 8)
        sz[g][q] = ((const float4*)&zpart_scr[(b*NCHUNK + g) * D])[q];
    __syncthreads();

    if (tid < 128) { sr0[tid] = 0.f; sr1[tid] = 0.f; }
    __syncthreads();
    if (tid < 75) {
        float4 z = make_float4(0.f, 0.f, 0.f, 0.f);
        #pragma unroll
        for (int gg = 0; gg < 8; gg++) {
            float4 p = sz[gg][tid];
            z.x += p.x; z.y += p.y; z.z += p.z; z.w += p.w;
        }
        float4 w0 = __ldg((const float4*)lin_w + tid);
        float4 w1 = __ldg((const float4*)(lin_w + D) + tid);
        sr0[tid] = z.x*w0.x + z.y*w0.y + z.z*w0.z + z.w*w0.w;
        sr1[tid] = z.x*w1.x + z.y*w1.y + z.z*w1.z + z.w*w1.w;
    }
    __syncthreads();
    for (int st = 64; st > 0; st >>= 1) {
        if (tid < st) { sr0[tid] += sr0[tid+st]; sr1[tid] += sr1[tid+st]; }
        __syncthreads();
    }
    if (tid == 0) {
        float a = sr0[0] + __ldg(lin_b + 0);
        float c = sr1[0] + __ldg(lin_b + 1);
        float m = fmaxf(a, c);
        float lse = m + logf(expf(a - m) + expf(c - m));
        out[b*2 + 0] = a - lse;
        out[b*2 + 1] = c - lse;
    }
}

// ---------------------------------------------------------------------------
extern "C" void kernel_launch(void* const* d_in, const int* in_sizes, int n_in,
                              void* d_out, int out_size) {
    const int*   inputs  = (const int*)  d_in[0];
    const float* emb     = (const float*)d_in[1];
    const float* cls     = (const float*)d_in[2];
    const float* conv_w  = (const float*)d_in[3];
    const float* conv_b  = (const float*)d_in[4];
    const float* lin_w   = (const float*)d_in[5];
    const float* lin_b   = (const float*)d_in[6];
    float* out = (float*)d_out;

    int beta_off = out_size - B*L;   // logits first, then beta [B,L]

    vocab_dot_kernel<<<(V + 31) / 32, 256>>>(emb, cls);                // 1563 blocks
    conv_exp_kernel<<<dim3(B, 2), 256>>>(inputs, conv_w, conv_b, out, beta_off);
    zacc_kernel<<<dim3(B, NCHUNK), 608>>>(inputs, emb, out, beta_off);
    logits_kernel<<<B, 608>>>(lin_w, lin_b, out);
}